// round 2
// baseline (speedup 1.0000x reference)
#include <cuda_runtime.h>
#include <cstdint>

#define TM       64
#define THREADS  256
#define IN_DIM   472
#define INP      480      // padded K
#define HID      128
#define MEMD     100
#define TIMED    100
#define EDGED    172
#define KC       16
#define NCHUNK   (INP / KC)   // 30

__device__ __forceinline__ unsigned long long pk2(float x, float y) {
    unsigned long long r;
    asm("mov.b64 %0, {%1, %2};" : "=l"(r) : "f"(x), "f"(y));
    return r;
}
__device__ __forceinline__ void upk2(unsigned long long v, float& x, float& y) {
    asm("mov.b64 {%0, %1}, %2;" : "=f"(x), "=f"(y) : "l"(v));
}
__device__ __forceinline__ void fma2(unsigned long long& d, unsigned long long a, unsigned long long b) {
    asm("fma.rn.f32x2 %0, %1, %2, %0;" : "+l"(d) : "l"(a), "l"(b));
}

__global__ void __launch_bounds__(THREADS, 1) tgn_kernel(
    const int*   __restrict__ src,  const int*   __restrict__ dst,
    const float* __restrict__ t,    const float* __restrict__ edge_attr,
    const float* __restrict__ memory, const float* __restrict__ last_update,
    const float* __restrict__ time_w, const float* __restrict__ time_b,
    const float* __restrict__ w1,   const float* __restrict__ b1,
    const float* __restrict__ w2,   const float* __restrict__ b2,
    float* __restrict__ out, int E)
{
    extern __shared__ float sm[];
    float* XS   = sm;                       // [TM][INP]
    float* WS   = XS + TM * INP;            // [2][KC][HID]
    float* TW   = WS + 2 * KC * HID;        // [TIMED]
    float* TB   = TW + TIMED;               // [TIMED]
    int*   SRCI = (int*)(TB + TIMED);       // [TM]
    int*   DSTI = SRCI + TM;                // [TM]
    float* DTS  = (float*)(DSTI + TM);      // [TM]

    const int tid = threadIdx.x;
    const int e0  = blockIdx.x * TM;

    // ---- prefetch W chunk 0 into registers (overlaps with gather) ----
    float4 wreg[2];
#pragma unroll
    for (int j = 0; j < 2; j++) {
        int v = tid + THREADS * j;            // 0..511 -> (row, col4)
        int row = v >> 5, c4 = v & 31;        // chunk 0: kglob = row < 16 (valid)
        wreg[j] = *reinterpret_cast<const float4*>(&w1[(size_t)row * HID + c4 * 4]);
    }

    // ---- per-row scalars + time-encoder params ----
    if (tid < TIMED) { TW[tid] = time_w[tid]; TB[tid] = time_b[tid]; }
    if (tid < TM) {
        int e = e0 + tid;
        int s = 0, d = 0; float dtv = 0.f;
        if (e < E) { s = src[e]; d = dst[e]; dtv = t[e] - last_update[s]; }
        SRCI[tid] = s; DSTI[tid] = d; DTS[tid] = dtv;
    }
    __syncthreads();

    // ---- Phase 1: gather full X tile into smem ----
    for (int i = tid; i < TM * MEMD; i += THREADS) {
        int r = i / MEMD, k = i - r * MEMD;
        bool valid = (e0 + r) < E;
        size_t sbase = (size_t)SRCI[r] * MEMD;
        size_t dbase = (size_t)DSTI[r] * MEMD;
        XS[r * INP + k]            = valid ? __ldg(&memory[sbase + k]) : 0.f;
        XS[r * INP + MEMD + k]     = valid ? __ldg(&memory[dbase + k]) : 0.f;
        XS[r * INP + 2 * MEMD + k] = valid ? cosf(fmaf(DTS[r], TW[k], TB[k])) : 0.f;
    }
    for (int i = tid; i < TM * EDGED; i += THREADS) {
        int r = i / EDGED, k = i - r * EDGED;
        XS[r * INP + 300 + k] = ((e0 + r) < E)
            ? edge_attr[(size_t)(e0 + r) * EDGED + k] : 0.f;
    }
    for (int i = tid; i < TM * (INP - IN_DIM); i += THREADS) {
        int r = i >> 3, k = i & 7;
        XS[r * INP + IN_DIM + k] = 0.f;
    }
    __syncthreads();

    // ---- Phase 2: register-tiled GEMM (f32x2 packed FMA) ----
    const int warp = tid >> 5, lane = tid & 31;
    const int rb = warp * 8;      // this warp's 8 rows
    const int cb = lane * 4;      // this lane's 4 cols

    unsigned long long acc[8][2];
#pragma unroll
    for (int i = 0; i < 8; i++) { acc[i][0] = 0ull; acc[i][1] = 0ull; }

    for (int c = 0; c < NCHUNK; c++) {
        float* W = WS + (c & 1) * KC * HID;
        // commit prefetched W chunk to smem
#pragma unroll
        for (int j = 0; j < 2; j++) {
            int v = tid + THREADS * j;
            *reinterpret_cast<float4*>(&W[(v >> 5) * HID + (v & 31) * 4]) = wreg[j];
        }
        // prefetch next chunk into registers
        if (c + 1 < NCHUNK) {
#pragma unroll
            for (int j = 0; j < 2; j++) {
                int v = tid + THREADS * j;
                int kglob = (c + 1) * KC + (v >> 5);
                if (kglob < IN_DIM)
                    wreg[j] = *reinterpret_cast<const float4*>(
                        &w1[(size_t)kglob * HID + (v & 31) * 4]);
                else
                    wreg[j] = make_float4(0.f, 0.f, 0.f, 0.f);
            }
        }
        __syncthreads();

#pragma unroll
        for (int g = 0; g < 4; g++) {
            float4 a[8];
#pragma unroll
            for (int i = 0; i < 8; i++)
                a[i] = *reinterpret_cast<const float4*>(&XS[(rb + i) * INP + c * KC + g * 4]);
#pragma unroll
            for (int kk = 0; kk < 4; kk++) {
                float4 bv = *reinterpret_cast<const float4*>(&W[(g * 4 + kk) * HID + cb]);
                unsigned long long b01 = pk2(bv.x, bv.y);
                unsigned long long b23 = pk2(bv.z, bv.w);
#pragma unroll
                for (int i = 0; i < 8; i++) {
                    float av = (kk == 0) ? a[i].x : (kk == 1) ? a[i].y
                             : (kk == 2) ? a[i].z : a[i].w;
                    unsigned long long aa = pk2(av, av);
                    fma2(acc[i][0], aa, b01);
                    fma2(acc[i][1], aa, b23);
                }
            }
        }
        // no trailing sync needed: next iteration's STS targets the other buffer,
        // and buffer reuse at c+2 is fenced by the sync at c+1.
    }

    // ---- Epilogue: bias + ReLU + w2 dot + warp reduce ----
    float4 b1v = *reinterpret_cast<const float4*>(&b1[cb]);
    float4 w2v = *reinterpret_cast<const float4*>(&w2[cb]);
    float bias2 = b2[0];

#pragma unroll
    for (int i = 0; i < 8; i++) {
        float h0, h1, h2, h3;
        upk2(acc[i][0], h0, h1);
        upk2(acc[i][1], h2, h3);
        h0 = fmaxf(h0 + b1v.x, 0.f);
        h1 = fmaxf(h1 + b1v.y, 0.f);
        h2 = fmaxf(h2 + b1v.z, 0.f);
        h3 = fmaxf(h3 + b1v.w, 0.f);
        float p = h0 * w2v.x + h1 * w2v.y + h2 * w2v.z + h3 * w2v.w;
#pragma unroll
        for (int o = 16; o > 0; o >>= 1)
            p += __shfl_xor_sync(0xffffffffu, p, o);
        int e = e0 + rb + i;
        if (lane == 0 && e < E) out[e] = p + bias2;
    }
}

extern "C" void kernel_launch(void* const* d_in, const int* in_sizes, int n_in,
                              void* d_out, int out_size)
{
    const int*   src         = (const int*)  d_in[0];
    const int*   dst         = (const int*)  d_in[1];
    const float* t           = (const float*)d_in[2];
    const float* edge_attr   = (const float*)d_in[3];
    const float* memory      = (const float*)d_in[4];
    const float* last_update = (const float*)d_in[5];
    const float* time_w      = (const float*)d_in[6];
    const float* time_b      = (const float*)d_in[7];
    const float* w1          = (const float*)d_in[8];
    const float* b1          = (const float*)d_in[9];
    const float* w2          = (const float*)d_in[10];
    const float* b2          = (const float*)d_in[11];
    float* out = (float*)d_out;

    const int E = in_sizes[0];
    const int smem_bytes = (TM * INP + 2 * KC * HID + 2 * TIMED) * 4 + TM * 12;

    cudaFuncSetAttribute(tgn_kernel, cudaFuncAttributeMaxDynamicSharedMemorySize, smem_bytes);

    int grid = (E + TM - 1) / TM;
    tgn_kernel<<<grid, THREADS, smem_bytes>>>(
        src, dst, t, edge_attr, memory, last_update,
        time_w, time_b, w1, b1, w2, b2, out, E);
}

// round 3
// speedup vs baseline: 1.0213x; 1.0213x over previous
#include <cuda_runtime.h>
#include <cstdint>

#define TM       64
#define THREADS  512
#define IN_DIM   472
#define INP      480      // padded K
#define HID      128
#define MEMD     100
#define TIMED    100
#define EDGED    172
#define KC       16
#define NCHUNK   (INP / KC)   // 30
#define WKS      20           // padded k-stride of transposed W tile

__device__ __forceinline__ void upk2(unsigned long long v, float& x, float& y) {
    asm("mov.b64 {%0, %1}, %2;" : "=f"(x), "=f"(y) : "l"(v));
}
__device__ __forceinline__ void fma2(unsigned long long& d, unsigned long long a, unsigned long long b) {
    asm("fma.rn.f32x2 %0, %1, %2, %0;" : "+l"(d) : "l"(a), "l"(b));
}

__global__ void __launch_bounds__(THREADS, 1) tgn_kernel(
    const int*   __restrict__ src,  const int*   __restrict__ dst,
    const float* __restrict__ t,    const float* __restrict__ edge_attr,
    const float* __restrict__ memory, const float* __restrict__ last_update,
    const float* __restrict__ time_w, const float* __restrict__ time_b,
    const float* __restrict__ w1,   const float* __restrict__ b1,
    const float* __restrict__ w2,   const float* __restrict__ b2,
    float* __restrict__ out, int E)
{
    extern __shared__ float sm[];
    float* XS   = sm;                        // [TM][INP]
    float* WS   = XS + TM * INP;             // [2][HID][WKS] transposed W chunk
    float* TW   = WS + 2 * HID * WKS;        // [TIMED]
    float* TB   = TW + TIMED;                // [TIMED]
    float* PART = TB + TIMED;                // [2][TM] epilogue partials
    int*   SRCI = (int*)(PART + 2 * TM);     // [TM]
    int*   DSTI = SRCI + TM;                 // [TM]
    float* DTS  = (float*)(DSTI + TM);       // [TM]

    const int tid   = threadIdx.x;
    const int eBase = blockIdx.x * TM;

    // ---- W prefetch assignment: thread -> (col, 4 consecutive k) ----
    const int wcol = tid & 127;          // 0..127
    const int wks  = (tid >> 7) << 2;    // 0,4,8,12
    float wr[4];
#pragma unroll
    for (int j = 0; j < 4; j++)          // chunk 0: k = wks+j < 16, always valid
        wr[j] = w1[(size_t)(wks + j) * HID + wcol];

    // ---- per-row scalars + time-encoder params ----
    if (tid < TIMED) { TW[tid] = time_w[tid]; TB[tid] = time_b[tid]; }
    if (tid < TM) {
        int e = eBase + tid;
        int s = 0, d = 0; float dtv = 0.f;
        if (e < E) { s = src[e]; d = dst[e]; dtv = t[e] - last_update[s]; }
        SRCI[tid] = s; DSTI[tid] = d; DTS[tid] = dtv;
    }
    __syncthreads();

    // ---- Phase 1: gather full X tile into smem ----
    for (int i = tid; i < TM * MEMD; i += THREADS) {
        int r = i / MEMD, k = i - r * MEMD;
        bool valid = (eBase + r) < E;
        size_t sbase = (size_t)SRCI[r] * MEMD;
        size_t dbase = (size_t)DSTI[r] * MEMD;
        XS[r * INP + k]            = valid ? __ldg(&memory[sbase + k]) : 0.f;
        XS[r * INP + MEMD + k]     = valid ? __ldg(&memory[dbase + k]) : 0.f;
        XS[r * INP + 2 * MEMD + k] = valid ? cosf(fmaf(DTS[r], TW[k], TB[k])) : 0.f;
    }
    for (int i = tid; i < TM * EDGED; i += THREADS) {
        int r = i / EDGED, k = i - r * EDGED;
        XS[r * INP + 300 + k] = ((eBase + r) < E)
            ? edge_attr[(size_t)(eBase + r) * EDGED + k] : 0.f;
    }
    {   // zero pad cols 472..479 : exactly one element per thread
        int r = tid >> 3, k = tid & 7;
        XS[r * INP + IN_DIM + k] = 0.f;
    }

    // ---- Phase 2: register-tiled GEMM, K-packed f32x2 FMA ----
    // 16 warps = 8 row-groups x 2 col-halves. Warp: 8 rows x 64 cols.
    // Lane covers cols {c0, c0+32}. acc pair = (even-k partial, odd-k partial).
    const int warp = tid >> 5, lane = tid & 31;
    const int rb = (warp >> 1) * 8;
    const int cg = warp & 1;
    const int c0 = cg * 64 + lane;

    unsigned long long acc[8][2];
#pragma unroll
    for (int i = 0; i < 8; i++) { acc[i][0] = 0ull; acc[i][1] = 0ull; }

    for (int c = 0; c < NCHUNK; c++) {
        float* W = WS + (c & 1) * HID * WKS;
        // commit prefetched W chunk, transposed: WS[col][k]
        *reinterpret_cast<float4*>(&W[wcol * WKS + wks]) =
            make_float4(wr[0], wr[1], wr[2], wr[3]);
        // prefetch next chunk
        if (c + 1 < NCHUNK) {
            int kb = (c + 1) * KC + wks;
#pragma unroll
            for (int j = 0; j < 4; j++)
                wr[j] = (kb + j < IN_DIM) ? w1[(size_t)(kb + j) * HID + wcol] : 0.f;
        }
        __syncthreads();

#pragma unroll
        for (int g = 0; g < 4; g++) {
            // W pairs for this lane's two columns: 4 k's = 2 packed kpairs each
            ulonglong2 wv0 = *reinterpret_cast<const ulonglong2*>(&W[c0 * WKS + g * 4]);
            ulonglong2 wv1 = *reinterpret_cast<const ulonglong2*>(&W[(c0 + 32) * WKS + g * 4]);
#pragma unroll
            for (int i = 0; i < 8; i++) {
                ulonglong2 av = *reinterpret_cast<const ulonglong2*>(
                    &XS[(rb + i) * INP + c * KC + g * 4]);
                fma2(acc[i][0], av.x, wv0.x);
                fma2(acc[i][0], av.y, wv0.y);
                fma2(acc[i][1], av.x, wv1.x);
                fma2(acc[i][1], av.y, wv1.y);
            }
        }
        // next iteration's STS targets the other W buffer; reuse at c+2 is
        // fenced by the sync at c+1.
    }

    // ---- Epilogue: fold halves + bias + ReLU + w2 dot + reduce ----
    float b1a = b1[c0],      b1b = b1[c0 + 32];
    float w2a = w2[c0],      w2b = w2[c0 + 32];

#pragma unroll
    for (int i = 0; i < 8; i++) {
        float e0, o0, e1, o1;
        upk2(acc[i][0], e0, o0);
        upk2(acc[i][1], e1, o1);
        float h0 = fmaxf(e0 + o0 + b1a, 0.f);
        float h1 = fmaxf(e1 + o1 + b1b, 0.f);
        float p = h0 * w2a + h1 * w2b;
#pragma unroll
        for (int o = 16; o > 0; o >>= 1)
            p += __shfl_xor_sync(0xffffffffu, p, o);
        if (lane == 0) PART[cg * TM + rb + i] = p;
    }
    __syncthreads();

    if (tid < TM) {
        int e = eBase + tid;
        if (e < E) out[e] = PART[tid] + PART[TM + tid] + b2[0];
    }
}

extern "C" void kernel_launch(void* const* d_in, const int* in_sizes, int n_in,
                              void* d_out, int out_size)
{
    const int*   src         = (const int*)  d_in[0];
    const int*   dst         = (const int*)  d_in[1];
    const float* t           = (const float*)d_in[2];
    const float* edge_attr   = (const float*)d_in[3];
    const float* memory      = (const float*)d_in[4];
    const float* last_update = (const float*)d_in[5];
    const float* time_w      = (const float*)d_in[6];
    const float* time_b      = (const float*)d_in[7];
    const float* w1          = (const float*)d_in[8];
    const float* b1          = (const float*)d_in[9];
    const float* w2          = (const float*)d_in[10];
    const float* b2          = (const float*)d_in[11];
    float* out = (float*)d_out;

    const int E = in_sizes[0];
    const int smem_bytes =
        (TM * INP + 2 * HID * WKS + 2 * TIMED + 2 * TM) * 4 + TM * 12;

    cudaFuncSetAttribute(tgn_kernel, cudaFuncAttributeMaxDynamicSharedMemorySize, smem_bytes);

    int grid = (E + TM - 1) / TM;
    tgn_kernel<<<grid, THREADS, smem_bytes>>>(
        src, dst, t, edge_attr, memory, last_update,
        time_w, time_b, w1, b1, w2, b2, out, E);
}

// round 5
// speedup vs baseline: 1.8595x; 1.8207x over previous
#include <cuda_runtime.h>
#include <cuda_bf16.h>
#include <cstdint>

#define TM       128
#define THREADS  512
#define IN_DIM   472
#define HID      128

#define AKS      264                    // padded k-stride (elems) per 256-k half
#define A_HI_OFF 0
#define A_LO_OFF (TM * AKS * 2)         // 67584
#define W_OFF    (2 * TM * AKS * 2)     // 135168
#define WBUF_STRIDE 36864               // one W chunk buffer (hi+lo)
#define WHL_STRIDE  18432               // hi->lo
#define WN_STRIDE   144                 // 72 bf16 per n-row
#define MISC     (W_OFF + 2 * WBUF_STRIDE)   // 208896
#define TW_OFF   (MISC)
#define TB_OFF   (MISC + 400)
#define B1_OFF   (MISC + 800)
#define W2_OFF   (MISC + 1312)
#define SRC_OFF  (MISC + 1824)
#define DST_OFF  (MISC + 2336)
#define DT_OFF   (MISC + 2848)
#define PART_OFF (MISC + 3360)
#define SMEM_BYTES (PART_OFF + 4 * 128 * 4)  // 214304

__device__ __align__(16) unsigned char g_w[262144];  // [hi|lo][128 n][512 k] bf16

// ---------------- helpers ----------------
__device__ __forceinline__ uint32_t smem_u32(const void* p) {
    uint32_t a;
    asm("{ .reg .u64 t; cvta.to.shared.u64 t, %1; cvt.u32.u64 %0, t; }" : "=r"(a) : "l"(p));
    return a;
}
__device__ __forceinline__ void ldsm4(uint32_t* r, uint32_t a) {
    asm volatile("ldmatrix.sync.aligned.m8n8.x4.shared.b16 {%0,%1,%2,%3}, [%4];"
        : "=r"(r[0]), "=r"(r[1]), "=r"(r[2]), "=r"(r[3]) : "r"(a));
}
__device__ __forceinline__ void mma16816(float* d, const uint32_t* a, uint32_t b0, uint32_t b1) {
    asm volatile("mma.sync.aligned.m16n8k16.row.col.f32.bf16.bf16.f32 "
        "{%0,%1,%2,%3}, {%4,%5,%6,%7}, {%8,%9}, {%0,%1,%2,%3};"
        : "+f"(d[0]), "+f"(d[1]), "+f"(d[2]), "+f"(d[3])
        : "r"(a[0]), "r"(a[1]), "r"(a[2]), "r"(a[3]), "r"(b0), "r"(b1));
}
__device__ __forceinline__ void cpasync16(uint32_t s, const void* g) {
    asm volatile("cp.async.cg.shared.global [%0], [%1], 16;" :: "r"(s), "l"(g) : "memory");
}
#define CP_COMMIT() asm volatile("cp.async.commit_group;" ::: "memory")
#define CP_WAIT0()  asm volatile("cp.async.wait_group 0;" ::: "memory")

// ---------------- W pre-split kernel ----------------
__global__ void wprep_kernel(const float* __restrict__ w1) {
    int i = blockIdx.x * blockDim.x + threadIdx.x;   // 65536
    int n = i >> 9, k = i & 511;
    float v = (k < IN_DIM) ? w1[(size_t)k * HID + n] : 0.f;
    __nv_bfloat16 h = __float2bfloat16(v);
    __nv_bfloat16 l = __float2bfloat16(v - __bfloat162float(h));
    *reinterpret_cast<__nv_bfloat16*>(g_w + ((size_t)n * 512 + k) * 2)          = h;
    *reinterpret_cast<__nv_bfloat16*>(g_w + 131072 + ((size_t)n * 512 + k) * 2) = l;
}

// ---------------- main fused kernel ----------------
__global__ void __launch_bounds__(THREADS, 1)
tgn_kernel(const int* __restrict__ src, const int* __restrict__ dst,
           const float* __restrict__ t, const float* __restrict__ edge_attr,
           const float* __restrict__ memory, const float* __restrict__ last_update,
           const float* __restrict__ time_w, const float* __restrict__ time_b,
           const float* __restrict__ b1, const float* __restrict__ w2,
           const float* __restrict__ b2, float* __restrict__ out, int E)
{
    extern __shared__ char sm[];
    const uint32_t smb = smem_u32(sm);
    const int tid  = threadIdx.x;
    const int wid  = tid >> 5;
    const int lane = tid & 31;
    const int eBase = blockIdx.x * TM;

    float* TW   = (float*)(sm + TW_OFF);
    float* TB   = (float*)(sm + TB_OFF);
    float* B1S  = (float*)(sm + B1_OFF);
    float* W2S  = (float*)(sm + W2_OFF);
    int*   SRCI = (int*)(sm + SRC_OFF);
    int*   DSTI = (int*)(sm + DST_OFF);
    float* DTS  = (float*)(sm + DT_OFF);
    float* PART = (float*)(sm + PART_OFF);

    // ---- issue W chunk 0 copy early (overlaps prologue + A build) ----
    auto issueW = [&](int g, int b) {
#pragma unroll
        for (int j = 0; j < 4; j++) {
            int idx = tid + THREADS * j;        // 0..2047
            int hl = idx >> 10, rem = idx & 1023;
            int n = rem >> 3, k8 = rem & 7;
            const char* gs = (const char*)g_w + hl * 131072
                           + ((size_t)n * 512 + g * 64 + k8 * 8) * 2;
            uint32_t sd = smb + W_OFF + b * WBUF_STRIDE + hl * WHL_STRIDE
                        + n * WN_STRIDE + k8 * 16;
            cpasync16(sd, gs);
        }
        CP_COMMIT();
    };
    issueW(0, 0);

    if (tid < 100) { TW[tid] = time_w[tid]; TB[tid] = time_b[tid]; }
    if (tid < HID) { B1S[tid] = b1[tid]; W2S[tid] = w2[tid]; }
    if (tid < TM) {
        int e = eBase + tid;
        int s = 0, d = 0; float dtv = 0.f;
        if (e < E) { s = src[e]; d = dst[e]; dtv = t[e] - last_update[s]; }
        SRCI[tid] = s; DSTI[tid] = d; DTS[tid] = dtv;
    }
    __syncthreads();

    const float2* m2 = reinterpret_cast<const float2*>(memory);
    const float2* e2 = reinterpret_cast<const float2*>(edge_attr);

    // ---- A build: gather + cos + hi/lo split into padded smem ----
    auto buildA = [&](int half) {
        for (int i = tid; i < TM * 128; i += THREADS) {
            int r = i >> 7, j = i & 127;
            float v0 = 0.f, v1 = 0.f;
            if ((eBase + r) < E) {
                if (half == 0) {
                    if (j < 50)       { float2 v = m2[(size_t)SRCI[r] * 50 + j];        v0 = v.x; v1 = v.y; }
                    else if (j < 100) { float2 v = m2[(size_t)DSTI[r] * 50 + (j - 50)]; v0 = v.x; v1 = v.y; }
                    else              { int tk = (j - 100) * 2; float dtv = DTS[r];
                                        v0 = cosf(fmaf(dtv, TW[tk], TB[tk]));
                                        v1 = cosf(fmaf(dtv, TW[tk + 1], TB[tk + 1])); }
                } else {
                    if (j < 22)       { int tk = 56 + j * 2; float dtv = DTS[r];
                                        v0 = cosf(fmaf(dtv, TW[tk], TB[tk]));
                                        v1 = cosf(fmaf(dtv, TW[tk + 1], TB[tk + 1])); }
                    else if (j < 108) { float2 v = e2[(size_t)(eBase + r) * 86 + (j - 22)]; v0 = v.x; v1 = v.y; }
                    // else zero pad (global k 472..511)
                }
            }
            __nv_bfloat16 h0 = __float2bfloat16(v0), h1 = __float2bfloat16(v1);
            __nv_bfloat16 l0 = __float2bfloat16(v0 - __bfloat162float(h0));
            __nv_bfloat16 l1 = __float2bfloat16(v1 - __bfloat162float(h1));
            __nv_bfloat162 hv; hv.x = h0; hv.y = h1;
            __nv_bfloat162 lv; lv.x = l0; lv.y = l1;
            uint32_t off = (uint32_t)r * (AKS * 2) + (uint32_t)j * 4;
            *reinterpret_cast<__nv_bfloat162*>(sm + A_HI_OFF + off) = hv;
            *reinterpret_cast<__nv_bfloat162*>(sm + A_LO_OFF + off) = lv;
        }
    };
    buildA(0);

    // ---- warp tile coordinates ----
    const int rm = (wid & 3) * 32;          // row group
    const int cn = (wid >> 2) * 32;         // col group
    const uint32_t aBase = smb + (uint32_t)(rm + (lane & 15)) * (AKS * 2)
                         + (uint32_t)((lane >> 4) << 4);
    const uint32_t bRow  = (uint32_t)(cn + ((lane >> 4) << 3) + (lane & 7)) * WN_STRIDE
                         + (uint32_t)(((lane >> 3) & 1) << 4);

    float acc[2][4][4];
#pragma unroll
    for (int ma = 0; ma < 2; ma++)
#pragma unroll
        for (int na = 0; na < 4; na++)
#pragma unroll
            for (int q = 0; q < 4; q++) acc[ma][na][q] = 0.f;

    for (int half = 0; half < 2; half++) {
        if (half == 1) { __syncthreads(); buildA(1); }
        for (int c = 0; c < 4; c++) {
            int g = half * 4 + c, buf = g & 1;
            CP_WAIT0();
            __syncthreads();                 // W[buf] ready; all mma(g-1) done
            if (g < 7) issueW(g + 1, buf ^ 1);

            const uint32_t bBase = smb + W_OFF + (uint32_t)buf * WBUF_STRIDE + bRow;
#pragma unroll
            for (int ks = 0; ks < 4; ks++) {
                uint32_t kb2 = (uint32_t)(c * 64 + ks * 16) * 2;
                uint32_t ah[8], al[8], bh[8], bl[8];
                ldsm4(ah,     aBase + kb2);
                ldsm4(ah + 4, aBase + 16 * (AKS * 2) + kb2);
                ldsm4(al,     aBase + A_LO_OFF + kb2);
                ldsm4(al + 4, aBase + A_LO_OFF + 16 * (AKS * 2) + kb2);
                ldsm4(bh,     bBase + ks * 32);
                ldsm4(bh + 4, bBase + 16 * WN_STRIDE + ks * 32);
                ldsm4(bl,     bBase + WHL_STRIDE + ks * 32);
                ldsm4(bl + 4, bBase + WHL_STRIDE + 16 * WN_STRIDE + ks * 32);
#pragma unroll
                for (int ma = 0; ma < 2; ma++)
#pragma unroll
                    for (int na = 0; na < 4; na++) {
                        float* d = acc[ma][na];
                        mma16816(d, ah + ma * 4, bh[na * 2], bh[na * 2 + 1]);
                        mma16816(d, ah + ma * 4, bl[na * 2], bl[na * 2 + 1]);
                        mma16816(d, al + ma * 4, bh[na * 2], bh[na * 2 + 1]);
                    }
            }
        }
    }

    // ---- epilogue: bias + ReLU + w2 dot, reduce over n ----
    float p[2][2] = {{0.f, 0.f}, {0.f, 0.f}};
#pragma unroll
    for (int ma = 0; ma < 2; ma++)
#pragma unroll
        for (int na = 0; na < 4; na++) {
            int n0 = cn + na * 8 + ((lane & 3) << 1);
            float b1a = B1S[n0], b1b = B1S[n0 + 1];
            float w2a = W2S[n0], w2b = W2S[n0 + 1];
            float* d = acc[ma][na];
            p[ma][0] += fmaxf(d[0] + b1a, 0.f) * w2a + fmaxf(d[1] + b1b, 0.f) * w2b;
            p[ma][1] += fmaxf(d[2] + b1a, 0.f) * w2a + fmaxf(d[3] + b1b, 0.f) * w2b;
        }
#pragma unroll
    for (int ma = 0; ma < 2; ma++)
#pragma unroll
        for (int rh = 0; rh < 2; rh++) {
            p[ma][rh] += __shfl_xor_sync(0xffffffffu, p[ma][rh], 1);
            p[ma][rh] += __shfl_xor_sync(0xffffffffu, p[ma][rh], 2);
        }
    if ((lane & 3) == 0) {
        int cw = wid >> 2;
        int r0 = rm + (lane >> 2);
        PART[cw * 128 + r0]      = p[0][0];
        PART[cw * 128 + r0 + 8]  = p[0][1];
        PART[cw * 128 + r0 + 16] = p[1][0];
        PART[cw * 128 + r0 + 24] = p[1][1];
    }
    __syncthreads();

    if (tid < TM) {
        int e = eBase + tid;
        if (e < E)
            out[e] = PART[tid] + PART[128 + tid] + PART[256 + tid] + PART[384 + tid] + b2[0];
    }
}

extern "C" void kernel_launch(void* const* d_in, const int* in_sizes, int n_in,
                              void* d_out, int out_size)
{
    const int*   src         = (const int*)  d_in[0];
    const int*   dst         = (const int*)  d_in[1];
    const float* t           = (const float*)d_in[2];
    const float* edge_attr   = (const float*)d_in[3];
    const float* memory      = (const float*)d_in[4];
    const float* last_update = (const float*)d_in[5];
    const float* time_w      = (const float*)d_in[6];
    const float* time_b      = (const float*)d_in[7];
    const float* w1          = (const float*)d_in[8];
    const float* b1          = (const float*)d_in[9];
    const float* w2          = (const float*)d_in[10];
    const float* b2          = (const float*)d_in[11];
    float* out = (float*)d_out;

    const int E = in_sizes[0];

    wprep_kernel<<<128, 512>>>(w1);

    cudaFuncSetAttribute(tgn_kernel, cudaFuncAttributeMaxDynamicSharedMemorySize, SMEM_BYTES);
    int grid = (E + TM - 1) / TM;
    tgn_kernel<<<grid, THREADS, SMEM_BYTES>>>(
        src, dst, t, edge_attr, memory, last_update,
        time_w, time_b, b1, w2, b2, out, E);
}